// round 3
// baseline (speedup 1.0000x reference)
#include <cuda_runtime.h>
#include <math.h>

// ---------------------------------------------------------------------------
// LSTM autoencoder: B=64, T=512, F=256, H=1024
//   init -> gemm(Xe) -> persistent encoder scan -> gemm(Xd)
//        -> persistent decoder scan -> gemm(out)
// 6 graph nodes total (R1's 1026 nodes made the driver's graph-upload pool
// retain 2MB after teardown -> rule violation).
// ---------------------------------------------------------------------------

#define TSTEPS 512
#define BATCH  64
#define FDIM   256
#define HDIM   1024
#define G4     4096
#define NCTA_SCAN 128

// Scratch in device globals (no allocation allowed).
__device__ float g_Xe  [134217728]; // [512][64][4096]
__device__ float g_Xd  [134217728]; // [512][64][4096]
__device__ float g_ench[33554432];  // [512][64][1024]
__device__ float g_dech[33554432];  // [512][64][1024]
__device__ float g_c   [BATCH * HDIM];
__device__ float g_h0  [BATCH * HDIM];
__device__ unsigned g_bar_gen;
__device__ unsigned g_bar_cnt;

__global__ void init_state_kernel() {
    int i = blockIdx.x * blockDim.x + threadIdx.x;
    if (i < BATCH * HDIM) { g_c[i] = 0.0f; g_h0[i] = 0.0f; }
    if (i == 0) { g_bar_gen = 0u; g_bar_cnt = 0u; }
}

// Sense-reversal grid barrier across the 128 co-resident scan CTAs.
__device__ __forceinline__ void grid_barrier() {
    __syncthreads();
    if (threadIdx.x == 0) {
        unsigned e = *(volatile unsigned*)&g_bar_gen;
        __threadfence();                       // release my CTA's writes
        unsigned a = atomicAdd(&g_bar_cnt, 1u);
        if (a == NCTA_SCAN - 1) {
            atomicExch(&g_bar_cnt, 0u);
            __threadfence();
            *(volatile unsigned*)&g_bar_gen = e + 1u;
        } else {
            while (*(volatile unsigned*)&g_bar_gen == e) { }
            __threadfence();                   // acquire
        }
    }
    __syncthreads();
}

// ---------------------------------------------------------------------------
// fp32 GEMM + bias: C[coff(m)+n] = bias[n] + sum_k A[aoff(m)+k] * W[n*K+k]
//   aoff(m) = (m&63)*a_sb + (m>>6)*a_st ; coff(m) = (m&63)*c_sb + (m>>6)*c_st
// Tile 128x128, K-chunk 8, 256 threads, 8x8 microtile (94% FFMA issue frac).
// Requires M%128==0, N%128==0, K%8==0.
// ---------------------------------------------------------------------------
__global__ void __launch_bounds__(256) gemm128_kernel(
    const float* __restrict__ A, const float* __restrict__ W,
    const float* __restrict__ bias, float* __restrict__ C,
    int K, int a_sb, int a_st, int c_sb, int c_st)
{
    __shared__ __align__(16) float As[8][132];
    __shared__ __align__(16) float Bs[8][132];

    const int m0t = blockIdx.y * 128;
    const int n0t = blockIdx.x * 128;
    const int tid = threadIdx.x;
    const int lm  = tid >> 1;          // 0..127 load row
    const int lk  = (tid & 1) * 4;     // 0 or 4
    const int mb  = (tid >> 4) * 8;    // compute row base 0..120
    const int nb  = (tid & 15) * 8;    // compute col base 0..120

    const int am = m0t + lm;
    const size_t aoff = (size_t)(am & 63) * a_sb + (size_t)(am >> 6) * a_st;
    const float* arow = A + aoff + lk;
    const float* wrow = W + (size_t)(n0t + lm) * K + lk;

    float acc[8][8] = {};

    // prologue: prefetch chunk 0
    float4 av = *(const float4*)(arow);
    float4 bv = *(const float4*)(wrow);

    const int nchunks = K >> 3;
    for (int ch = 0; ch < nchunks; ch++) {
        __syncthreads();   // previous compute done before overwrite
        As[lk + 0][lm] = av.x; As[lk + 1][lm] = av.y;
        As[lk + 2][lm] = av.z; As[lk + 3][lm] = av.w;
        Bs[lk + 0][lm] = bv.x; Bs[lk + 1][lm] = bv.y;
        Bs[lk + 2][lm] = bv.z; Bs[lk + 3][lm] = bv.w;
        __syncthreads();
        if (ch + 1 < nchunks) {
            av = *(const float4*)(arow + (ch + 1) * 8);
            bv = *(const float4*)(wrow + (ch + 1) * 8);
        }
#pragma unroll
        for (int q = 0; q < 8; q++) {
            float4 a0 = *(const float4*)&As[q][mb];
            float4 a1 = *(const float4*)&As[q][mb + 4];
            float4 b0 = *(const float4*)&Bs[q][nb];
            float4 b1 = *(const float4*)&Bs[q][nb + 4];
            float ar[8] = {a0.x, a0.y, a0.z, a0.w, a1.x, a1.y, a1.z, a1.w};
            float br[8] = {b0.x, b0.y, b0.z, b0.w, b1.x, b1.y, b1.z, b1.w};
#pragma unroll
            for (int r = 0; r < 8; r++)
#pragma unroll
                for (int c = 0; c < 8; c++)
                    acc[r][c] += ar[r] * br[c];
        }
    }

    float4 bi0 = *(const float4*)(bias + n0t + nb);
    float4 bi1 = *(const float4*)(bias + n0t + nb + 4);
    const float bb[8] = {bi0.x, bi0.y, bi0.z, bi0.w, bi1.x, bi1.y, bi1.z, bi1.w};

#pragma unroll
    for (int r = 0; r < 8; r++) {
        int m = m0t + mb + r;
        size_t cbase = (size_t)(m & 63) * c_sb + (size_t)(m >> 6) * c_st
                     + n0t + nb;
        float4 o0 = make_float4(acc[r][0] + bb[0], acc[r][1] + bb[1],
                                acc[r][2] + bb[2], acc[r][3] + bb[3]);
        float4 o1 = make_float4(acc[r][4] + bb[4], acc[r][5] + bb[5],
                                acc[r][6] + bb[6], acc[r][7] + bb[7]);
        *(float4*)(C + cbase)     = o0;
        *(float4*)(C + cbase + 4) = o1;
    }
}

// ---------------------------------------------------------------------------
// Persistent LSTM scan: one kernel runs all 512 steps.
// CTA j (0..127) owns h columns [j*8, j*8+8) => 32 gate columns.
// Whh slice (32 cols x 1024 k = 128KB) loaded to smem ONCE.
// Per step: gates = Xp + Hin @ Whh_slice^T ; activations ; c,h update.
// Cross-CTA h handoff via Hser time-series buffer + grid barrier.
// smem: Ws[1024][36] (147456B) + Hb 2x[32][68] (17408B) = 164864B.
// ---------------------------------------------------------------------------
__global__ void __launch_bounds__(256) lstm_scan_kernel(
    const float* __restrict__ Hin0,     // [64][1024] initial h
    const float* __restrict__ Xp_base,  // [512][64][4096] input-part (+bias)
    const float* __restrict__ Whh,      // [4096][1024]
    float* __restrict__ cbuf,           // [64][1024] persistent cell state
    float* __restrict__ Hser)           // [512][64][1024] per-step h out
{
    extern __shared__ float sm[];
    float* Ws = sm;            // [k][c] stride 36 -> 36864 floats
    float* Hb = sm + 36864;    // 2 x [kc][m] stride 68 -> 2x2176 floats

    const int j   = blockIdx.x;
    const int jc0 = j * 8;
    const int tid = threadIdx.x;

    // one-time: Whh slice -> smem, layout Ws[k*36 + c]
    {
        int c = tid >> 3;                                  // 0..31
        int gcol = (c >> 3) * HDIM + jc0 + (c & 7);
        const float* wr = Whh + (size_t)gcol * HDIM;
        for (int k0 = (tid & 7) * 4; k0 < HDIM; k0 += 32) {
            float4 w = *(const float4*)(wr + k0);
            Ws[(k0 + 0) * 36 + c] = w.x;
            Ws[(k0 + 1) * 36 + c] = w.y;
            Ws[(k0 + 2) * 36 + c] = w.z;
            Ws[(k0 + 3) * 36 + c] = w.w;
        }
    }

    // compute mapping: thread -> rows m0..m0+1, cols c0..c0+3 (of 64x32 tile)
    const int m0    = (tid >> 3) * 2;                      // 0..62
    const int c0    = (tid & 7) * 4;                       // 0..28
    const int gcol0 = (c0 >> 3) * HDIM + jc0 + (c0 & 7);   // global gate col
    // H-chunk load mapping: row mL, k offset kq within 32-k chunk
    const int mL = tid >> 2;                               // 0..63
    const int kq = (tid & 3) * 8;                          // 0,8,16,24

    const float* Hin = Hin0;
    for (int t = 0; t < TSTEPS; t++) {
        const float* Xp   = Xp_base + (size_t)t * (BATCH * G4);
        float*       Hout = Hser    + (size_t)t * (BATCH * HDIM);

        float a00 = 0.f, a01 = 0.f, a02 = 0.f, a03 = 0.f;
        float a10 = 0.f, a11 = 0.f, a12 = 0.f, a13 = 0.f;

        const float* hrow = Hin + mL * HDIM + kq;
        float4 p0 = *(const float4*)(hrow);
        float4 p1 = *(const float4*)(hrow + 4);

        for (int ch = 0; ch < 32; ch++) {
            float* HB = Hb + (ch & 1) * 2176;
            __syncthreads();                    // buf free (read 2 chunks ago)
            HB[(kq + 0) * 68 + mL] = p0.x;
            HB[(kq + 1) * 68 + mL] = p0.y;
            HB[(kq + 2) * 68 + mL] = p0.z;
            HB[(kq + 3) * 68 + mL] = p0.w;
            HB[(kq + 4) * 68 + mL] = p1.x;
            HB[(kq + 5) * 68 + mL] = p1.y;
            HB[(kq + 6) * 68 + mL] = p1.z;
            HB[(kq + 7) * 68 + mL] = p1.w;
            __syncthreads();
            if (ch < 31) {
                const float* hp = hrow + (ch + 1) * 32;
                p0 = *(const float4*)(hp);
                p1 = *(const float4*)(hp + 4);
            }
            const float* wp = Ws + (ch * 32) * 36 + c0;
            const float* hq = HB + m0;
#pragma unroll
            for (int kc = 0; kc < 32; kc++) {
                float2 h = *(const float2*)(hq + kc * 68);
                float4 w = *(const float4*)(wp + kc * 36);
                a00 += h.x * w.x; a01 += h.x * w.y;
                a02 += h.x * w.z; a03 += h.x * w.w;
                a10 += h.y * w.x; a11 += h.y * w.y;
                a12 += h.y * w.z; a13 += h.y * w.w;
            }
        }

        // add input part; stage pre-activations to Gx (reuse Hb buf0: its
        // last reader finished before the ch=31 top syncthreads)
        float4 x0 = *(const float4*)(Xp + (size_t)m0 * G4 + gcol0);
        float4 x1 = *(const float4*)(Xp + (size_t)(m0 + 1) * G4 + gcol0);
        float* Gx = Hb;                          // [64][33] = 2112 <= 2176
        Gx[m0 * 33 + c0 + 0] = a00 + x0.x;
        Gx[m0 * 33 + c0 + 1] = a01 + x0.y;
        Gx[m0 * 33 + c0 + 2] = a02 + x0.z;
        Gx[m0 * 33 + c0 + 3] = a03 + x0.w;
        Gx[(m0 + 1) * 33 + c0 + 0] = a10 + x1.x;
        Gx[(m0 + 1) * 33 + c0 + 1] = a11 + x1.y;
        Gx[(m0 + 1) * 33 + c0 + 2] = a12 + x1.z;
        Gx[(m0 + 1) * 33 + c0 + 3] = a13 + x1.w;
        __syncthreads();

        // activations: 512 (m, cj) outputs, 2 per thread
#pragma unroll
        for (int u = 0; u < 2; u++) {
            int pid = tid * 2 + u;
            int m  = pid >> 3;
            int cj = pid & 7;
            float gi = Gx[m * 33 + cj];
            float gf = Gx[m * 33 + 8 + cj];
            float gg = Gx[m * 33 + 16 + cj];
            float go = Gx[m * 33 + 24 + cj];
            float ii = 1.0f / (1.0f + __expf(-gi));
            float ff = 1.0f / (1.0f + __expf(-gf));
            float tg = tanhf(gg);
            float oo = 1.0f / (1.0f + __expf(-go));
            int idx  = m * HDIM + jc0 + cj;
            float cn = ff * cbuf[idx] + ii * tg;
            cbuf[idx] = cn;
            Hout[idx] = oo * tanhf(cn);
        }

        grid_barrier();          // publish Hout to all CTAs for step t+1
        Hin = Hout;
    }
}

// ---------------------------------------------------------------------------
extern "C" void kernel_launch(void* const* d_in, const int* in_sizes, int n_in,
                              void* d_out, int out_size)
{
    const float* x      = (const float*)d_in[0]; // [64,512,256]
    const float* W_ih_e = (const float*)d_in[1]; // [4096,256]
    const float* W_hh_e = (const float*)d_in[2]; // [4096,1024]
    const float* b_e    = (const float*)d_in[3]; // [4096]
    const float* W_ih_d = (const float*)d_in[4]; // [4096,1024]
    const float* W_hh_d = (const float*)d_in[5]; // [4096,1024]
    const float* b_d    = (const float*)d_in[6]; // [4096]
    const float* W_out  = (const float*)d_in[7]; // [256,1024]
    const float* b_out  = (const float*)d_in[8]; // [256]
    float* out = (float*)d_out;                  // [64,512,256]

    float *Xe, *Xd, *ench, *dech, *cbuf, *h0;
    cudaGetSymbolAddress((void**)&Xe,   g_Xe);
    cudaGetSymbolAddress((void**)&Xd,   g_Xd);
    cudaGetSymbolAddress((void**)&ench, g_ench);
    cudaGetSymbolAddress((void**)&dech, g_dech);
    cudaGetSymbolAddress((void**)&cbuf, g_c);
    cudaGetSymbolAddress((void**)&h0,   g_h0);

    const int SCAN_SMEM = (36864 + 2 * 2176) * 4;   // 164864 bytes
    cudaFuncSetAttribute(lstm_scan_kernel,
                         cudaFuncAttributeMaxDynamicSharedMemorySize, SCAN_SMEM);

    // reset h0/c/barrier state (deterministic across graph replays)
    init_state_kernel<<<256, 256>>>();

    // Xe[t,b,:] = x[b,t,:] @ W_ih_e^T + b_e   (m = t*64+b)
    gemm128_kernel<<<dim3(G4 / 128, (TSTEPS * BATCH) / 128), 256>>>(
        x, W_ih_e, b_e, Xe, FDIM, 131072, 256, 4096, 262144);

    // encoder scan (persistent, 512 steps)
    lstm_scan_kernel<<<NCTA_SCAN, 256, SCAN_SMEM>>>(h0, Xe, W_hh_e, cbuf, ench);

    // Xd = enc_hs @ W_ih_d^T + b_d   (enc_hs is [t][b][h])
    gemm128_kernel<<<dim3(G4 / 128, (TSTEPS * BATCH) / 128), 256>>>(
        ench, W_ih_d, b_d, Xd, HDIM, 1024, 65536, 4096, 262144);

    // decoder scan: seeded by enc_hs[511] (= h_T) and cbuf (= c_T)
    lstm_scan_kernel<<<NCTA_SCAN, 256, SCAN_SMEM>>>(
        ench + (size_t)(TSTEPS - 1) * (BATCH * HDIM), Xd, W_hh_d, cbuf, dech);

    // out[b,t,:] = dec_hs[t,b,:] @ W_out^T + b_out
    gemm128_kernel<<<dim3(FDIM / 128, (TSTEPS * BATCH) / 128), 256>>>(
        dech, W_out, b_out, out, HDIM, 1024, 65536, 131072, 256);
}